// round 6
// baseline (speedup 1.0000x reference)
#include <cuda_runtime.h>
#include <cstdint>

#define NGROUPS 512   // B*S/16
#define NSLOTS  64    // E*Sets
#define DDIM    512
#define TTOK    16
#define FDIM    32

typedef unsigned long long ull;
union U2 { ull u; float2 f; };

// packed fp32x2 FMA (sm_100+): d.lo += a.lo*b.lo ; d.hi += a.hi*b.hi
__device__ __forceinline__ void ffma2(ull& d, ull a, ull b) {
    asm("fma.rn.f32x2 %0, %1, %2, %0;" : "+l"(d) : "l"(a), "l"(b));
}
__device__ __forceinline__ ull bcast2(float x) {
    ull r; asm("mov.b64 %0, {%1, %1};" : "=l"(r) : "f"(x)); return r;
}
__device__ __forceinline__ ull pack2(float lo, float hi) {
    ull r; asm("mov.b64 %0, {%1, %2};" : "=l"(r) : "f"(lo), "f"(hi)); return r;
}

__device__ int g_winners[NGROUPS * NSLOTS];

// ---------------------------------------------------------------------------
// Kernel 1: routing (unchanged — proven exact: FFMA2 main path + cooperative
// fp64 recheck of near-ties). Also zero-inits the output tile.
// ---------------------------------------------------------------------------
__global__ __launch_bounds__(256) void k_route(const float* __restrict__ x,
                                               const float* __restrict__ ctrl,
                                               float* __restrict__ out)
{
    extern __shared__ float sm[];
    float* xs   = sm;                        // 16 x 512 tokens (32 KB)
    float* part = sm + 8192;                 // 256 x 16 partials (16 KB)
    float* ls   = sm + 12288;                // 64 x 16 logits (4 KB)
    double* dred = (double*)(sm + 13312);    // 256 doubles (2 KB)
    __shared__ int sflags[64];
    __shared__ int swin[64];
    __shared__ int snf;
    __shared__ double dlog[16];

    const int G   = blockIdx.x;
    const int tid = threadIdx.x;
    if (tid == 0) snf = 0;

    const float4* src = (const float4*)(x + (size_t)G * 8192);
    float4* dst = (float4*)(out + (size_t)G * 8192);
    float4* xs4 = (float4*)xs;
    const float4 z4 = make_float4(0.f, 0.f, 0.f, 0.f);
    for (int i = tid; i < 2048; i += 256) { xs4[i] = src[i]; dst[i] = z4; }
    __syncthreads();

    {
        const int sq = tid & 15;
        const int tq = (tid >> 4) & 3;
        const int ks = tid >> 6;
        const int kbase = ks * 128;
        U2 acc[4][2];
        #pragma unroll
        for (int t = 0; t < 4; ++t) { acc[t][0].u = 0ull; acc[t][1].u = 0ull; }
        const float* cbase = ctrl + sq * 4;
        const float* x0 = xs + tq * 4 * DDIM;
        for (int kk = 0; kk < 128; kk += 4) {
            const int k = kbase + kk;
            ulonglong2 w[4];
            #pragma unroll
            for (int j = 0; j < 4; ++j)
                w[j] = __ldg((const ulonglong2*)(cbase + (size_t)(k + j) * 64));
            float xv[4][4];
            #pragma unroll
            for (int t = 0; t < 4; ++t)
                *(float4*)&xv[t][0] = *(const float4*)(x0 + t * DDIM + k);
            #pragma unroll
            for (int j = 0; j < 4; ++j) {
                #pragma unroll
                for (int t = 0; t < 4; ++t) {
                    ull xb = bcast2(xv[t][j]);
                    ffma2(acc[t][0].u, xb, w[j].x);
                    ffma2(acc[t][1].u, xb, w[j].y);
                }
            }
        }
        #pragma unroll
        for (int t = 0; t < 4; ++t) {
            part[tid * 16 + t * 4 + 0] = acc[t][0].f.x;
            part[tid * 16 + t * 4 + 1] = acc[t][0].f.y;
            part[tid * 16 + t * 4 + 2] = acc[t][1].f.x;
            part[tid * 16 + t * 4 + 3] = acc[t][1].f.y;
        }
    }
    __syncthreads();

    {
        const int s   = tid & 63;
        const int tq2 = tid >> 6;
        const int sq2 = s >> 2, sl = s & 3;
        const float step = 1e-6f / 15.f;
        #pragma unroll
        for (int tl = 0; tl < 4; ++tl) {
            float v = 0.f;
            #pragma unroll
            for (int c = 0; c < 4; ++c)
                v += part[(c * 64 + tq2 * 16 + sq2) * 16 + tl * 4 + sl];
            const int t = tq2 * 4 + tl;
            ls[s * 16 + t] = v + step * (float)t;
        }
    }
    __syncthreads();

    if (tid < 64) {
        const int s = tid;
        float best = -3.4e38f, second = -3.4e38f;
        int bi = 0;
        #pragma unroll
        for (int t = 0; t < TTOK; ++t) {
            float v = ls[s * 16 + t];
            if (v >= best) { second = best; best = v; bi = t; }
            else if (v > second) { second = v; }
        }
        swin[s] = bi;
        if (best - second < 2e-5f) { int p = atomicAdd(&snf, 1); sflags[p] = s; }
    }
    __syncthreads();

    const int nf = snf;
    for (int i = 0; i < nf; ++i) {
        const int s = sflags[i];
        const int t = tid >> 4, j = tid & 15;
        double a = 0.0;
        const float* xr = xs + t * DDIM + j * 32;
        const float* cp = ctrl + (size_t)(j * 32) * 64 + s;
        #pragma unroll 8
        for (int k = 0; k < 32; ++k)
            a += (double)xr[k] * (double)__ldg(cp + (size_t)k * 64);
        dred[t * 16 + j] = a;
        __syncthreads();
        if (tid < 16) {
            double tot = 0.0;
            #pragma unroll
            for (int j2 = 0; j2 < 16; ++j2) tot += dred[tid * 16 + j2];
            dlog[tid] = tot + (double)tid * (1e-6 / 15.0);
        }
        __syncthreads();
        if (tid == 0) {
            double best = -1e300; int bi = 0;
            #pragma unroll
            for (int t2 = 0; t2 < TTOK; ++t2)
                if (dlog[t2] >= best) { best = dlog[t2]; bi = t2; }
            swin[s] = bi;
        }
        __syncthreads();
    }
    if (tid < 64) g_winners[G * 64 + tid] = swin[tid];
}

// ---------------------------------------------------------------------------
// Kernel 2: per-slot expert FFN. Grid (8, 64): CTA = (slot, 64 groups).
// GEMM1: warp = 8 rows, lane = f. x streamed from global (warp-uniform
// LDG.128, each element read exactly once); f1 staged in double-buffered
// smem chunks pre-paired for FFMA2 (conflict-free LDS.64). No k-split.
// GEMM2: warp = 64-d chunk, 4 passes of 16 rows (32 acc regs); f2 from L1/L2;
// float2 atomic scatter.
// ---------------------------------------------------------------------------
#define ROWS 64
#define YPAD 68     // YT row stride (floats); 4-bank offset, 16B aligned

__global__ __launch_bounds__(256, 3) void k_expert(const float* __restrict__ x,
                                                   const float* __restrict__ f1,
                                                   const float* __restrict__ f2,
                                                   float* __restrict__ out)
{
    __shared__ ull   wb[2][32][32];      // [buf][k2][f] paired f1 (16 KB)
    __shared__ float YT[32 * YPAD];      // [f][row] relu'd Y (8.7 KB)
    __shared__ int   rowb[ROWS];

    const int slot = blockIdx.y;
    const int g0   = blockIdx.x * ROWS;
    const int tid  = threadIdx.x;
    const int wid  = tid >> 5;
    const int lane = tid & 31;

    if (tid < ROWS) {
        const int g = g0 + tid;
        rowb[tid] = (g * TTOK + g_winners[g * 64 + slot]) * DDIM;
    }

    // --- stage helper data (producer mapping: k2 = tid>>3, fq = tid&7)
    const int sk2 = tid >> 3;
    const int sfq = tid & 7;
    const float* f1base = f1 + slot * 32 + sfq * 4;

    // stage chunk 0
    {
        const float* p0 = f1base + (size_t)(2 * sk2) * 2048;
        const float4 a = __ldg((const float4*)p0);
        const float4 b = __ldg((const float4*)(p0 + 2048));
        wb[0][sk2][sfq * 4 + 0] = pack2(a.x, b.x);
        wb[0][sk2][sfq * 4 + 1] = pack2(a.y, b.y);
        wb[0][sk2][sfq * 4 + 2] = pack2(a.z, b.z);
        wb[0][sk2][sfq * 4 + 3] = pack2(a.w, b.w);
    }
    __syncthreads();

    // ---- GEMM1: warp owns rows 8*wid..8*wid+7, lane = f, full k sweep
    {
        const float* xp[8];
        #pragma unroll
        for (int r = 0; r < 8; ++r) xp[r] = x + rowb[wid * 8 + r];

        U2 acc[8];
        #pragma unroll
        for (int r = 0; r < 8; ++r) acc[r].u = 0ull;

        for (int c = 0; c < 8; ++c) {
            // prefetch next chunk into the other buffer
            if (c < 7) {
                const float* p0 = f1base + (size_t)((c + 1) * 64 + 2 * sk2) * 2048;
                const float4 a = __ldg((const float4*)p0);
                const float4 b = __ldg((const float4*)(p0 + 2048));
                const int nb = (c + 1) & 1;
                wb[nb][sk2][sfq * 4 + 0] = pack2(a.x, b.x);
                wb[nb][sk2][sfq * 4 + 1] = pack2(a.y, b.y);
                wb[nb][sk2][sfq * 4 + 2] = pack2(a.z, b.z);
                wb[nb][sk2][sfq * 4 + 3] = pack2(a.w, b.w);
            }
            const int cb = c & 1;
            const int k0 = c * 64;
            #pragma unroll 4
            for (int kq = 0; kq < 16; ++kq) {
                const ull w0 = wb[cb][2 * kq    ][lane];   // (k, k+1)
                const ull w1 = wb[cb][2 * kq + 1][lane];   // (k+2, k+3)
                #pragma unroll
                for (int r = 0; r < 8; ++r) {
                    const ulonglong2 xv =
                        *(const ulonglong2*)(xp[r] + k0 + kq * 4);
                    ffma2(acc[r].u, xv.x, w0);
                    ffma2(acc[r].u, xv.y, w1);
                }
            }
            __syncthreads();
        }
        // relu + write YT[f][row]
        #pragma unroll
        for (int r = 0; r < 8; ++r)
            YT[lane * YPAD + wid * 8 + r] = fmaxf(acc[r].f.x + acc[r].f.y, 0.f);
    }
    __syncthreads();

    // ---- GEMM2: warp owns d0..d0+63 (lane: 2 d); 4 passes of 16 rows
    {
        const int d0 = wid * 64 + lane * 2;
        const float* w2p = f2 + slot * (FDIM * DDIM) + d0;

        #pragma unroll
        for (int pass = 0; pass < 4; ++pass) {
            U2 acc[8][2];
            #pragma unroll
            for (int p = 0; p < 8; ++p) { acc[p][0].u = 0ull; acc[p][1].u = 0ull; }

            #pragma unroll 4
            for (int k = 0; k < FDIM; ++k) {
                const float2 wv = __ldg((const float2*)(w2p + k * DDIM));
                const ull wb0 = bcast2(wv.x);
                const ull wb1 = bcast2(wv.y);
                const ulonglong2* yp =
                    (const ulonglong2*)(YT + k * YPAD + pass * 16);
                #pragma unroll
                for (int q = 0; q < 4; ++q) {
                    const ulonglong2 y = yp[q];   // rows (4q,4q+1),(4q+2,4q+3)
                    ffma2(acc[2*q  ][0].u, y.x, wb0);
                    ffma2(acc[2*q  ][1].u, y.x, wb1);
                    ffma2(acc[2*q+1][0].u, y.y, wb0);
                    ffma2(acc[2*q+1][1].u, y.y, wb1);
                }
            }
            #pragma unroll
            for (int p = 0; p < 8; ++p) {
                const int r0 = pass * 16 + 2 * p;
                atomicAdd((float2*)(out + rowb[r0    ] + d0),
                          make_float2(acc[p][0].f.x, acc[p][1].f.x));
                atomicAdd((float2*)(out + rowb[r0 + 1] + d0),
                          make_float2(acc[p][0].f.y, acc[p][1].f.y));
            }
        }
    }
}

// ---------------------------------------------------------------------------
extern "C" void kernel_launch(void* const* d_in, const int* in_sizes, int n_in,
                              void* d_out, int out_size)
{
    (void)in_sizes; (void)n_in; (void)out_size;
    const float* x    = (const float*)d_in[0];
    const float* ctrl = (const float*)d_in[1];
    const float* f1   = (const float*)d_in[2];
    const float* f2   = (const float*)d_in[3];
    float* out = (float*)d_out;

    const int smem1 = 13312 * 4 + 2048;   // 55296
    cudaFuncSetAttribute(k_route, cudaFuncAttributeMaxDynamicSharedMemorySize, smem1);

    k_route<<<NGROUPS, 256, smem1>>>(x, ctrl, out);
    k_expert<<<dim3(8, 64), 256>>>(x, f1, f2, out);
}

// round 8
// speedup vs baseline: 1.2387x; 1.2387x over previous
#include <cuda_runtime.h>
#include <cstdint>

#define NGROUPS 512   // B*S/16
#define NSLOTS  64    // E*Sets
#define DDIM    512
#define TTOK    16
#define FDIM    32

typedef unsigned long long ull;
union U2 { ull u; float2 f; };

// packed fp32x2 FMA (route kernel)
__device__ __forceinline__ void ffma2(ull& d, ull a, ull b) {
    asm("fma.rn.f32x2 %0, %1, %2, %0;" : "+l"(d) : "l"(a), "l"(b));
}
__device__ __forceinline__ ull bcast2(float x) {
    ull r; asm("mov.b64 %0, {%1, %1};" : "=l"(r) : "f"(x)); return r;
}

__device__ int g_winners[NGROUPS * NSLOTS];

// ---------------------------------------------------------------------------
// tf32 helpers
// ---------------------------------------------------------------------------
__device__ __forceinline__ uint32_t tf32hi(float v) {
    uint32_t r; asm("cvt.rna.tf32.f32 %0, %1;" : "=r"(r) : "f"(v)); return r;
}
__device__ __forceinline__ void split_tf32(float v, uint32_t& h, uint32_t& l) {
    h = tf32hi(v);
    l = tf32hi(v - __uint_as_float(h));
}
__device__ __forceinline__ void mma8(float* c, uint32_t a0, uint32_t a1,
                                     uint32_t a2, uint32_t a3,
                                     uint32_t b0, uint32_t b1) {
    asm volatile("mma.sync.aligned.m16n8k8.row.col.f32.tf32.tf32.f32 "
                 "{%0,%1,%2,%3}, {%4,%5,%6,%7}, {%8,%9}, {%0,%1,%2,%3};"
                 : "+f"(c[0]), "+f"(c[1]), "+f"(c[2]), "+f"(c[3])
                 : "r"(a0), "r"(a1), "r"(a2), "r"(a3), "r"(b0), "r"(b1));
}
__device__ __forceinline__ uint32_t ulo(ull v) { return (uint32_t)v; }
__device__ __forceinline__ uint32_t uhi(ull v) { return (uint32_t)(v >> 32); }

// ---------------------------------------------------------------------------
// Kernel 1: routing (unchanged — proven exact; ~2us). Zero-inits out.
// ---------------------------------------------------------------------------
__global__ __launch_bounds__(256) void k_route(const float* __restrict__ x,
                                               const float* __restrict__ ctrl,
                                               float* __restrict__ out)
{
    extern __shared__ float sm[];
    float* xs   = sm;
    float* part = sm + 8192;
    float* ls   = sm + 12288;
    double* dred = (double*)(sm + 13312);
    __shared__ int sflags[64];
    __shared__ int swin[64];
    __shared__ int snf;
    __shared__ double dlog[16];

    const int G   = blockIdx.x;
    const int tid = threadIdx.x;
    if (tid == 0) snf = 0;

    const float4* src = (const float4*)(x + (size_t)G * 8192);
    float4* dst = (float4*)(out + (size_t)G * 8192);
    float4* xs4 = (float4*)xs;
    const float4 z4 = make_float4(0.f, 0.f, 0.f, 0.f);
    for (int i = tid; i < 2048; i += 256) { xs4[i] = src[i]; dst[i] = z4; }
    __syncthreads();

    {
        const int sq = tid & 15;
        const int tq = (tid >> 4) & 3;
        const int ks = tid >> 6;
        const int kbase = ks * 128;
        U2 acc[4][2];
        #pragma unroll
        for (int t = 0; t < 4; ++t) { acc[t][0].u = 0ull; acc[t][1].u = 0ull; }
        const float* cbase = ctrl + sq * 4;
        const float* x0 = xs + tq * 4 * DDIM;
        for (int kk = 0; kk < 128; kk += 4) {
            const int k = kbase + kk;
            ulonglong2 w[4];
            #pragma unroll
            for (int j = 0; j < 4; ++j)
                w[j] = __ldg((const ulonglong2*)(cbase + (size_t)(k + j) * 64));
            float xv[4][4];
            #pragma unroll
            for (int t = 0; t < 4; ++t)
                *(float4*)&xv[t][0] = *(const float4*)(x0 + t * DDIM + k);
            #pragma unroll
            for (int j = 0; j < 4; ++j) {
                #pragma unroll
                for (int t = 0; t < 4; ++t) {
                    ull xb = bcast2(xv[t][j]);
                    ffma2(acc[t][0].u, xb, w[j].x);
                    ffma2(acc[t][1].u, xb, w[j].y);
                }
            }
        }
        #pragma unroll
        for (int t = 0; t < 4; ++t) {
            part[tid * 16 + t * 4 + 0] = acc[t][0].f.x;
            part[tid * 16 + t * 4 + 1] = acc[t][0].f.y;
            part[tid * 16 + t * 4 + 2] = acc[t][1].f.x;
            part[tid * 16 + t * 4 + 3] = acc[t][1].f.y;
        }
    }
    __syncthreads();

    {
        const int s   = tid & 63;
        const int tq2 = tid >> 6;
        const int sq2 = s >> 2, sl = s & 3;
        const float step = 1e-6f / 15.f;
        #pragma unroll
        for (int tl = 0; tl < 4; ++tl) {
            float v = 0.f;
            #pragma unroll
            for (int c = 0; c < 4; ++c)
                v += part[(c * 64 + tq2 * 16 + sq2) * 16 + tl * 4 + sl];
            const int t = tq2 * 4 + tl;
            ls[s * 16 + t] = v + step * (float)t;
        }
    }
    __syncthreads();

    if (tid < 64) {
        const int s = tid;
        float best = -3.4e38f, second = -3.4e38f;
        int bi = 0;
        #pragma unroll
        for (int t = 0; t < TTOK; ++t) {
            float v = ls[s * 16 + t];
            if (v >= best) { second = best; best = v; bi = t; }
            else if (v > second) { second = v; }
        }
        swin[s] = bi;
        if (best - second < 2e-5f) { int p = atomicAdd(&snf, 1); sflags[p] = s; }
    }
    __syncthreads();

    const int nf = snf;
    for (int i = 0; i < nf; ++i) {
        const int s = sflags[i];
        const int t = tid >> 4, j = tid & 15;
        double a = 0.0;
        const float* xr = xs + t * DDIM + j * 32;
        const float* cp = ctrl + (size_t)(j * 32) * 64 + s;
        #pragma unroll 8
        for (int k = 0; k < 32; ++k)
            a += (double)xr[k] * (double)__ldg(cp + (size_t)k * 64);
        dred[t * 16 + j] = a;
        __syncthreads();
        if (tid < 16) {
            double tot = 0.0;
            #pragma unroll
            for (int j2 = 0; j2 < 16; ++j2) tot += dred[tid * 16 + j2];
            dlog[tid] = tot + (double)tid * (1e-6 / 15.0);
        }
        __syncthreads();
        if (tid == 0) {
            double best = -1e300; int bi = 0;
            #pragma unroll
            for (int t2 = 0; t2 < TTOK; ++t2)
                if (dlog[t2] >= best) { best = dlog[t2]; bi = t2; }
            swin[s] = bi;
        }
        __syncthreads();
    }
    if (tid < 64) g_winners[G * 64 + tid] = swin[tid];
}

// ---------------------------------------------------------------------------
// Kernel 2: tf32 mma.sync expert. CTA = (slot, 64 groups), 256 thr / 8 warps.
// Split precision (hi/lo tf32, 3 mma per logical). Operands staged in smem
// pre-split and (k,k+4)-paired as 8B words; fragment loads are LDS.64 with
// strides == 4 (mod 16 ull) => conflict-free.
//   pairing: P = (k>>3)*4 + (k&3), half = (k>>2)&1.
// Byte offsets in dynamic smem:
//   rowb  @ 0      (256 B)
//   B1h   @ 256    [32P][36] ull  (9216)     B1l @ 9472
//   Yh    @ 18688  [16P][68] ull  (8704)     Yl  @ 27392
//   X/B2  @ 36096  Xh[32P][68] (17408), Xl @ 53504  (B2h/B2l alias @36096/52992)
// total 70912 B
// ---------------------------------------------------------------------------
#define OFF_ROWB 0
#define OFF_B1H  256
#define OFF_B1L  9472
#define OFF_YH   18688
#define OFF_YL   27392
#define OFF_XH   36096
#define OFF_XL   53504
#define OFF_B2H  36096
#define OFF_B2L  52992
#define SMEM2    70912

__global__ __launch_bounds__(256) void k_expert(const float* __restrict__ x,
                                                const float* __restrict__ f1,
                                                const float* __restrict__ f2,
                                                float* __restrict__ out)
{
    extern __shared__ __align__(16) char smraw[];
    int*       rowb  = (int*)(smraw + OFF_ROWB);
    uint32_t*  B1h32 = (uint32_t*)(smraw + OFF_B1H);
    uint32_t*  B1l32 = (uint32_t*)(smraw + OFF_B1L);
    uint32_t*  Yh32  = (uint32_t*)(smraw + OFF_YH);
    uint32_t*  Yl32  = (uint32_t*)(smraw + OFF_YL);
    uint32_t*  Xh32  = (uint32_t*)(smraw + OFF_XH);
    uint32_t*  Xl32  = (uint32_t*)(smraw + OFF_XL);
    uint32_t*  B2h32 = (uint32_t*)(smraw + OFF_B2H);
    uint32_t*  B2l32 = (uint32_t*)(smraw + OFF_B2L);
    const ull* B1h_u = (const ull*)(smraw + OFF_B1H);
    const ull* B1l_u = (const ull*)(smraw + OFF_B1L);
    const ull* Yh_u  = (const ull*)(smraw + OFF_YH);
    const ull* Yl_u  = (const ull*)(smraw + OFF_YL);
    const ull* Xh_u  = (const ull*)(smraw + OFF_XH);
    const ull* Xl_u  = (const ull*)(smraw + OFF_XL);
    const ull* B2h_u = (const ull*)(smraw + OFF_B2H);
    const ull* B2l_u = (const ull*)(smraw + OFF_B2L);

    const int slot = blockIdx.y;
    const int g0   = blockIdx.x * 64;
    const int tid  = threadIdx.x;
    const int wid  = tid >> 5;
    const int lane = tid & 31;
    const int gq   = lane >> 2;   // fragment group row 0..7
    const int c4   = lane & 3;    // fragment group col 0..3

    if (tid < 64) {
        const int gg = g0 + tid;
        rowb[tid] = (gg * TTOK + g_winners[gg * 64 + slot]) * DDIM;
    }
    __syncthreads();

    // ================= GEMM1: C[64,32] = X[64,512] @ f1slc[512,32] =========
    const int mt  = wid & 3;            // m-tile (16 rows)
    const int m0  = mt * 16;
    const int ntb = (wid >> 2) * 2;     // 2 n-tiles of 8

    float acc1[2][4];
    #pragma unroll
    for (int j = 0; j < 2; ++j)
        #pragma unroll
        for (int e = 0; e < 4; ++e) acc1[j][e] = 0.f;

    for (int cb = 0; cb < 8; ++cb) {
        const int kb = cb * 64;
        // --- stage X chunk [64 rows][64 k] split+paired
        {
            const int r  = tid >> 2;
            const int kq = (tid & 3) * 16;
            const float* xp = x + rowb[r] + kb + kq;
            #pragma unroll
            for (int q = 0; q < 4; ++q) {
                const float4 v = __ldg((const float4*)(xp + q * 4));
                const float vv[4] = {v.x, v.y, v.z, v.w};
                #pragma unroll
                for (int e = 0; e < 4; ++e) {
                    const int k = kq + q * 4 + e;
                    const int P = ((k >> 3) << 2) | (k & 3);
                    const int hf = (k >> 2) & 1;
                    uint32_t h, l; split_tf32(vv[e], h, l);
                    const int idx = (P * 68 + r) * 2 + hf;
                    Xh32[idx] = h; Xl32[idx] = l;
                }
            }
        }
        // --- stage f1 chunk [64 k][32 f] split+paired
        {
            const int k  = tid >> 2;
            const int f0 = (tid & 3) * 8;
            const float* fp = f1 + (size_t)(kb + k) * 2048 + slot * 32 + f0;
            const int P  = ((k >> 3) << 2) | (k & 3);
            const int hf = (k >> 2) & 1;
            #pragma unroll
            for (int q = 0; q < 2; ++q) {
                const float4 v = __ldg((const float4*)fp + q);
                const float vv[4] = {v.x, v.y, v.z, v.w};
                #pragma unroll
                for (int e = 0; e < 4; ++e) {
                    const int f = f0 + q * 4 + e;
                    uint32_t h, l; split_tf32(vv[e], h, l);
                    const int idx = (P * 36 + f) * 2 + hf;
                    B1h32[idx] = h; B1l32[idx] = l;
                }
            }
        }
        __syncthreads();

        // --- compute: 8 k-steps x 2 n-tiles x 3 mma
        #pragma unroll
        for (int k8 = 0; k8 < 8; ++k8) {
            const int Pb = k8 * 4 + c4;
            const ull ah0 = Xh_u[Pb * 68 + m0 + gq];
            const ull ah1 = Xh_u[Pb * 68 + m0 + 8 + gq];
            const ull al0 = Xl_u[Pb * 68 + m0 + gq];
            const ull al1 = Xl_u[Pb * 68 + m0 + 8 + gq];
            #pragma unroll
            for (int j = 0; j < 2; ++j) {
                const int n0 = (ntb + j) * 8;
                const ull bh = B1h_u[Pb * 36 + n0 + gq];
                const ull bl = B1l_u[Pb * 36 + n0 + gq];
                mma8(acc1[j], ulo(ah0), ulo(ah1), uhi(ah0), uhi(ah1), ulo(bh), uhi(bh));
                mma8(acc1[j], ulo(ah0), ulo(ah1), uhi(ah0), uhi(ah1), ulo(bl), uhi(bl));
                mma8(acc1[j], ulo(al0), ulo(al1), uhi(al0), uhi(al1), ulo(bh), uhi(bh));
            }
        }
        __syncthreads();
    }

    // --- relu + split -> Y (paired over f) ---------------------------------
    #pragma unroll
    for (int j = 0; j < 2; ++j) {
        const int n0 = (ntb + j) * 8;
        #pragma unroll
        for (int e = 0; e < 4; ++e) {
            const int f   = n0 + 2 * c4 + (e & 1);
            const int row = m0 + gq + ((e >> 1) << 3);
            const int P   = ((f >> 3) << 2) | (f & 3);
            const int hf  = (f >> 2) & 1;
            uint32_t h, l; split_tf32(fmaxf(acc1[j][e], 0.f), h, l);
            const int idx = (P * 68 + row) * 2 + hf;
            Yh32[idx] = h; Yl32[idx] = l;
        }
    }
    __syncthreads();

    // ================= GEMM2: Out[64,512] = Y[64,32] @ f2slc[32,512] =======
    const int nh = wid >> 2;            // 0/1: 64-n half within 128-n chunk
    for (int nc = 0; nc < 4; ++nc) {
        // --- stage f2 chunk [32 k][128 n] split+paired (aliases X region)
        {
            const int k   = tid >> 3;
            const int n0s = (tid & 7) * 16;
            const float* fp = f2 + (size_t)slot * (FDIM * DDIM) + (size_t)k * DDIM
                              + nc * 128 + n0s;
            const int P  = ((k >> 3) << 2) | (k & 3);
            const int hf = (k >> 2) & 1;
            #pragma unroll
            for (int q = 0; q < 4; ++q) {
                const float4 v = __ldg((const float4*)(fp + q * 4));
                const float vv[4] = {v.x, v.y, v.z, v.w};
                #pragma unroll
                for (int e = 0; e < 4; ++e) {
                    const int n = n0s + q * 4 + e;
                    uint32_t h, l; split_tf32(vv[e], h, l);
                    const int idx = (P * 132 + n) * 2 + hf;
                    B2h32[idx] = h; B2l32[idx] = l;
                }
            }
        }
        __syncthreads();

        // --- preload Y fragments (all 4 k-steps)
        ull yh0[4], yh1[4], yl0[4], yl1[4];
        #pragma unroll
        for (int k8 = 0; k8 < 4; ++k8) {
            const int Pb = k8 * 4 + c4;
            yh0[k8] = Yh_u[Pb * 68 + m0 + gq];
            yh1[k8] = Yh_u[Pb * 68 + m0 + 8 + gq];
            yl0[k8] = Yl_u[Pb * 68 + m0 + gq];
            yl1[k8] = Yl_u[Pb * 68 + m0 + 8 + gq];
        }

        // --- 8 n-tiles of 8; compute + immediate atomic scatter
        #pragma unroll 2
        for (int nt = 0; nt < 8; ++nt) {
            const int n0 = nh * 64 + nt * 8;
            float acc[4] = {0.f, 0.f, 0.f, 0.f};
            #pragma unroll
            for (int k8 = 0; k8 < 4; ++k8) {
                const int Pb = k8 * 4 + c4;
                const ull bh = B2h_u[Pb * 132 + n0 + gq];
                const ull bl = B2l_u[Pb * 132 + n0 + gq];
                mma8(acc, ulo(yh0[k8]), ulo(yh1[k8]), uhi(yh0[k8]), uhi(yh1[k8]), ulo(bh), uhi(bh));
                mma8(acc, ulo(yh0[k8]), ulo(yh1[k8]), uhi(yh0[k8]), uhi(yh1[k8]), ulo(bl), uhi(bl));
                mma8(acc, ulo(yl0[k8]), ulo(yl1[k8]), uhi(yl0[k8]), uhi(yl1[k8]), ulo(bh), uhi(bh));
            }
            const int d = nc * 128 + n0 + 2 * c4;
            atomicAdd((float2*)(out + rowb[m0 + gq]     + d), make_float2(acc[0], acc[1]));
            atomicAdd((float2*)(out + rowb[m0 + 8 + gq] + d), make_float2(acc[2], acc[3]));
        }
        __syncthreads();
    }
}

// ---------------------------------------------------------------------------
extern "C" void kernel_launch(void* const* d_in, const int* in_sizes, int n_in,
                              void* d_out, int out_size)
{
    (void)in_sizes; (void)n_in; (void)out_size;
    const float* x    = (const float*)d_in[0];
    const float* ctrl = (const float*)d_in[1];
    const float* f1   = (const float*)d_in[2];
    const float* f2   = (const float*)d_in[3];
    float* out = (float*)d_out;

    const int smem1 = 13312 * 4 + 2048;   // 55296
    cudaFuncSetAttribute(k_route,  cudaFuncAttributeMaxDynamicSharedMemorySize, smem1);
    cudaFuncSetAttribute(k_expert, cudaFuncAttributeMaxDynamicSharedMemorySize, SMEM2);

    k_route<<<NGROUPS, 256, smem1>>>(x, ctrl, out);
    k_expert<<<dim3(8, 64), 256, SMEM2>>>(x, f1, f2, out);
}